// round 1
// baseline (speedup 1.0000x reference)
#include <cuda_runtime.h>
#include <math.h>

#define BATCH 16
#define CIN   128
#define LIN   8192
#define LOUT  16384
#define COUT  128
#define NJ    384            // CIN * Q(=3) power channels
#define MT    64             // original-m positions per tile (=> 128 output positions)
#define NTILES (LIN / MT)    // 128
#define PCOLS 66             // MT + 2 halo columns
#define PPITCH 68            // padded pitch
#define KC    8              // A-chunk depth (j's per staged chunk)

// Scratch (no allocation allowed in kernel_launch)
__device__ float g_Acomb[NJ * COUT * 4];          // [j][co]{Ae0, Ae1, Ao0, Ao1}
__device__ float g_psum  [BATCH * NTILES * COUT]; // per-tile sums
__device__ float g_psumsq[BATCH * NTILES * COUT]; // per-tile sums of squares
__device__ float g_stats [BATCH * COUT * 2];      // {mean, rstd}

// ---------------------------------------------------------------------------
// Kernel 1: fold the K=3 conv over the 2x-upsampled signal into two 2-tap
// convs over the original signal:
//   even: out[2m]   = W0*p[m-1] + (W1+W2)*p[m]
//   odd:  out[2m+1] = (W0+W1)*p[m] + W2*p[m+1]
// ---------------------------------------------------------------------------
__global__ void prep_weights(const float* __restrict__ W) {
    int idx = blockIdx.x * blockDim.x + threadIdx.x;
    if (idx >= NJ * COUT) return;
    int j = idx / COUT, co = idx % COUT;
    const float* w = W + ((size_t)co * NJ + j) * 3;   // W[co][j][k]
    float w0 = w[0], w1 = w[1], w2 = w[2];
    float4 v = make_float4(w0, w1 + w2, w0 + w1, w2);
    ((float4*)g_Acomb)[j * COUT + co] = v;
}

// ---------------------------------------------------------------------------
// Kernel 2: the fused upsample+powers+conv GEMM.
// Grid: (NTILES, BATCH), 256 threads. Per-thread microtile: 8 co x 4 m x 2 par.
// ---------------------------------------------------------------------------
__global__ __launch_bounds__(256, 1)
void conv_kernel(const float* __restrict__ x,
                 const float* __restrict__ bias,
                 float* __restrict__ out) {
    extern __shared__ float smem[];
    float*  sP = smem;                              // NJ x PPITCH powers
    float4* sA = (float4*)(smem + NJ * PPITCH);     // KC x COUT float4 chunk

    const int b    = blockIdx.y;
    const int tile = blockIdx.x;
    const int m0   = tile * MT;
    const int tid  = threadIdx.x;

    // ---- Load x tile (with halo) and compute powers into SMEM ----
    const float* xb = x + (size_t)b * CIN * LIN;
    for (int idx = tid; idx < CIN * PCOLS; idx += 256) {
        int ci = idx / PCOLS, c = idx % PCOLS;
        int m  = m0 - 1 + c;
        float v = (m >= 0 && m < LIN) ? xb[(size_t)ci * LIN + m] : 0.f;
        float v2 = v * v;
        sP[(0 * CIN + ci) * PPITCH + c] = v;
        sP[(1 * CIN + ci) * PPITCH + c] = v2;
        sP[(2 * CIN + ci) * PPITCH + c] = v2 * v;
    }

    const int tr  = tid >> 4;      // 0..15 -> co block
    const int tc  = tid & 15;      // 0..15 -> m block
    const int co0 = tr * 8;

    float acE[8][4], acO[8][4];
    #pragma unroll
    for (int u = 0; u < 8; u++)
        #pragma unroll
        for (int i = 0; i < 4; i++) { acE[u][i] = 0.f; acO[u][i] = 0.f; }

    const float4* gA = (const float4*)g_Acomb;

    for (int kk = 0; kk < NJ; kk += KC) {
        __syncthreads();                 // protects sP (first iter) + sA reuse
        #pragma unroll
        for (int t = 0; t < (KC * COUT) / 256; t++) {
            int i4 = tid + t * 256;
            sA[i4] = gA[kk * COUT + i4];
        }
        __syncthreads();

        #pragma unroll
        for (int jj = 0; jj < KC; jj++) {
            const float* pr = &sP[(kk + jj) * PPITCH + tc * 4];
            float p0 = pr[0], p1 = pr[1], p2 = pr[2],
                  p3 = pr[3], p4 = pr[4], p5 = pr[5];
            #pragma unroll
            for (int u = 0; u < 8; u++) {
                float4 a = sA[jj * COUT + co0 + u];
                acE[u][0] += a.x * p0;  acE[u][0] += a.y * p1;
                acE[u][1] += a.x * p1;  acE[u][1] += a.y * p2;
                acE[u][2] += a.x * p2;  acE[u][2] += a.y * p3;
                acE[u][3] += a.x * p3;  acE[u][3] += a.y * p4;
                acO[u][0] += a.z * p1;  acO[u][0] += a.w * p2;
                acO[u][1] += a.z * p2;  acO[u][1] += a.w * p3;
                acO[u][2] += a.z * p3;  acO[u][2] += a.w * p4;
                acO[u][3] += a.z * p4;  acO[u][3] += a.w * p5;
            }
        }
    }

    // ---- Epilogue: bias, coalesced float4 stores, per-tile stats ----
    const int posBase = 2 * m0 + tc * 8;   // 8 consecutive output positions
    #pragma unroll
    for (int u = 0; u < 8; u++) {
        int co = co0 + u;
        float bv = __ldg(&bias[co]);
        float e0 = acE[u][0] + bv, o0 = acO[u][0] + bv;
        float e1 = acE[u][1] + bv, o1 = acO[u][1] + bv;
        float e2 = acE[u][2] + bv, o2 = acO[u][2] + bv;
        float e3 = acE[u][3] + bv, o3 = acO[u][3] + bv;

        float4* orow = (float4*)(out + ((size_t)(b * COUT + co)) * LOUT + posBase);
        orow[0] = make_float4(e0, o0, e1, o1);
        orow[1] = make_float4(e2, o2, e3, o3);

        float s  = e0 + o0 + e1 + o1 + e2 + o2 + e3 + o3;
        float ss = e0*e0 + o0*o0 + e1*e1 + o1*o1 + e2*e2 + o2*o2 + e3*e3 + o3*o3;
        #pragma unroll
        for (int off = 8; off > 0; off >>= 1) {
            s  += __shfl_down_sync(0xffffffffu, s,  off, 16);
            ss += __shfl_down_sync(0xffffffffu, ss, off, 16);
        }
        if (tc == 0) {
            int pidx = (b * NTILES + tile) * COUT + co;
            g_psum[pidx]   = s;
            g_psumsq[pidx] = ss;
        }
    }
}

// ---------------------------------------------------------------------------
// Kernel 3: reduce per-tile partials -> mean, rstd (fp64 accumulation)
// ---------------------------------------------------------------------------
__global__ void reduce_stats() {
    int idx = blockIdx.x * blockDim.x + threadIdx.x;  // b*COUT + co
    if (idx >= BATCH * COUT) return;
    int b = idx / COUT, co = idx % COUT;
    double s = 0.0, ss = 0.0;
    for (int t = 0; t < NTILES; t++) {
        int pidx = (b * NTILES + t) * COUT + co;
        s  += (double)g_psum[pidx];
        ss += (double)g_psumsq[pidx];
    }
    double mean = s / (double)LOUT;
    double var  = ss / (double)LOUT - mean * mean;
    g_stats[idx * 2 + 0] = (float)mean;
    g_stats[idx * 2 + 1] = (float)(1.0 / sqrt(var + 1e-5));
}

// ---------------------------------------------------------------------------
// Kernel 4: normalize + tanh, float4 grid-stride
// ---------------------------------------------------------------------------
__global__ void norm_tanh(float* __restrict__ out) {
    const int total4 = BATCH * COUT * LOUT / 4;
    float4* o4 = (float4*)out;
    for (int idx4 = blockIdx.x * blockDim.x + threadIdx.x; idx4 < total4;
         idx4 += gridDim.x * blockDim.x) {
        int row = idx4 >> 12;                 // LOUT/4 = 4096 float4 per row
        float mean = g_stats[row * 2 + 0];
        float rstd = g_stats[row * 2 + 1];
        float4 v = o4[idx4];
        v.x = tanhf((v.x - mean) * rstd);
        v.y = tanhf((v.y - mean) * rstd);
        v.z = tanhf((v.z - mean) * rstd);
        v.w = tanhf((v.w - mean) * rstd);
        o4[idx4] = v;
    }
}

// ---------------------------------------------------------------------------
extern "C" void kernel_launch(void* const* d_in, const int* in_sizes, int n_in,
                              void* d_out, int out_size) {
    const float* x    = (const float*)d_in[0];
    const float* W    = (const float*)d_in[1];
    const float* bias = (const float*)d_in[2];
    float* out = (float*)d_out;

    const int smem_bytes = (NJ * PPITCH + KC * COUT * 4) * (int)sizeof(float);
    cudaFuncSetAttribute(conv_kernel,
                         cudaFuncAttributeMaxDynamicSharedMemorySize, smem_bytes);

    prep_weights<<<(NJ * COUT + 255) / 256, 256>>>(W);
    conv_kernel<<<dim3(NTILES, BATCH), 256, smem_bytes>>>(x, bias, out);
    reduce_stats<<<(BATCH * COUT + 255) / 256, 256>>>();
    norm_tanh<<<8192, 256>>>(out);
}

// round 3
// speedup vs baseline: 3.1640x; 3.1640x over previous
#include <cuda_runtime.h>
#include <cuda_fp16.h>
#include <math.h>
#include <stdint.h>

#define BATCH 16
#define CIN   128
#define LIN   8192
#define LOUT  16384
#define COUT  128
#define NMT   128                // original-m per CTA tile (-> 256 outputs)
#define NT    (LIN / NMT)        // 64 tiles per batch
#define KTOT  768                // 2 taps * 384 power-channels
#define KC    64                 // K per chunk
#define NCHUNK (KTOT / KC)       // 12
#define PA    72                 // A smem pitch (halves): 144B, conflict-free ldmatrix
#define PB    136                // B smem pitch (halves): 272B, conflict-free ldmatrix

// ---------------- scratch (no allocs allowed) ----------------
__device__ __half g_Ae[COUT * KTOT];               // folded even weights [co][k]
__device__ __half g_Ao[COUT * KTOT];               // folded odd  weights [co][k]
__device__ float  g_psum  [BATCH * NT * COUT];
__device__ float  g_psumsq[BATCH * NT * COUT];
__device__ float  g_stats [BATCH * COUT * 2];

// SMEM layout (bytes)
#define OFF_AE  0
#define OFF_AO  (OFF_AE + 128 * PA * 2)            // 18432
#define OFF_BE  (OFF_AO + 128 * PA * 2)            // 36864
#define OFF_BO  (OFF_BE + 64 * PB * 2)             // 54272
#define OFF_WS  (OFF_BO + 64 * PB * 2)             // 71680
#define OFF_WSQ (OFF_WS + 16 * 32 * 4)             // 73728
#define SM_TOTAL (OFF_WSQ + 16 * 32 * 4)           // 75776

// ---------------- PTX helpers (family-portable only) ----------------
__device__ __forceinline__ uint32_t smem_u32(const void* p) {
    uint32_t a;
    asm("{ .reg .u64 t; cvta.to.shared.u64 t, %1; cvt.u32.u64 %0, t; }" : "=r"(a) : "l"(p));
    return a;
}
__device__ __forceinline__ void ldsm_x4(uint32_t* r, uint32_t addr) {
    asm volatile("ldmatrix.sync.aligned.m8n8.x4.shared.b16 {%0,%1,%2,%3}, [%4];"
        : "=r"(r[0]), "=r"(r[1]), "=r"(r[2]), "=r"(r[3]) : "r"(addr));
}
__device__ __forceinline__ void ldsm_x4t(uint32_t* r, uint32_t addr) {
    asm volatile("ldmatrix.sync.aligned.m8n8.x4.trans.shared.b16 {%0,%1,%2,%3}, [%4];"
        : "=r"(r[0]), "=r"(r[1]), "=r"(r[2]), "=r"(r[3]) : "r"(addr));
}
__device__ __forceinline__ void mma16816(float* d, const uint32_t* a, uint32_t b0, uint32_t b1) {
    asm volatile("mma.sync.aligned.m16n8k16.row.col.f32.f16.f16.f32 "
        "{%0,%1,%2,%3}, {%4,%5,%6,%7}, {%8,%9}, {%0,%1,%2,%3};"
        : "+f"(d[0]), "+f"(d[1]), "+f"(d[2]), "+f"(d[3])
        : "r"(a[0]), "r"(a[1]), "r"(a[2]), "r"(a[3]), "r"(b0), "r"(b1));
}

// ---------------------------------------------------------------------------
// Kernel 1: fold W into fp16 even/odd weight images, K interleaved as 2j+tap.
//   even: out[2m]   = W0*p[m-1] + (W1+W2)*p[m]
//   odd:  out[2m+1] = (W0+W1)*p[m] + W2*p[m+1]
// ---------------------------------------------------------------------------
__global__ void prep_weights(const float* __restrict__ W) {
    int idx = blockIdx.x * blockDim.x + threadIdx.x;
    if (idx >= COUT * 384) return;
    int co = idx / 384, j = idx % 384;
    const float* wp = W + (size_t)idx * 3;            // W[co][j][k]
    float w0 = wp[0], w1 = wp[1], w2 = wp[2];
    g_Ae[co * KTOT + 2 * j + 0] = __float2half_rn(w0);
    g_Ae[co * KTOT + 2 * j + 1] = __float2half_rn(w1 + w2);
    g_Ao[co * KTOT + 2 * j + 0] = __float2half_rn(w0 + w1);
    g_Ao[co * KTOT + 2 * j + 1] = __float2half_rn(w2);
}

// ---------------------------------------------------------------------------
// Kernel 2: HMMA conv. Grid (NT, BATCH), 512 threads = 16 warps.
// Warp = 32co x 32m x both parities.
// ---------------------------------------------------------------------------
__global__ __launch_bounds__(512, 1)
void conv_kernel(const float* __restrict__ x,
                 const float* __restrict__ bias,
                 float* __restrict__ out) {
    extern __shared__ char smem[];
    __half* sAe = (__half*)(smem + OFF_AE);
    __half* sAo = (__half*)(smem + OFF_AO);
    __half* sBe = (__half*)(smem + OFF_BE);
    __half* sBo = (__half*)(smem + OFF_BO);
    float*  sWS  = (float*)(smem + OFF_WS);
    float*  sWSq = (float*)(smem + OFF_WSQ);

    const int b    = blockIdx.y;
    const int tile = blockIdx.x;
    const int m0   = tile * NMT;
    const int tid  = threadIdx.x;
    const int lane = tid & 31;
    const int w    = tid >> 5;
    const int costrip = w >> 2;          // 0..3
    const int mq      = w & 3;           // 0..3
    const int co0   = costrip * 32;
    const int mbase = mq * 32;

    const uint32_t sb = smem_u32(smem);
    const uint32_t aRow  = lane & 15;
    const uint32_t aColq = lane >> 4;
    const uint32_t aE0 = sb + OFF_AE + ((co0 + aRow) * PA + aColq * 8) * 2;
    const uint32_t aO0 = sb + OFF_AO + ((co0 + aRow) * PA + aColq * 8) * 2;
    const uint32_t bE0 = sb + OFF_BE + (aRow * PB + mbase + aColq * 8) * 2;
    const uint32_t bO0 = sb + OFF_BO + (aRow * PB + mbase + aColq * 8) * 2;

    float acc[2][2][4][4];               // [parity][mt][nt][reg]
    #pragma unroll
    for (int p = 0; p < 2; p++)
        #pragma unroll
        for (int mt = 0; mt < 2; mt++)
            #pragma unroll
            for (int nt = 0; nt < 4; nt++)
                #pragma unroll
                for (int r = 0; r < 4; r++) acc[p][mt][nt][r] = 0.f;

    const float* xb = x + (size_t)b * CIN * LIN;

    for (int c = 0; c < NCHUNK; c++) {
        __syncthreads();                 // prev chunk's mma done before overwrite

        // ---- stage A chunk: 128 rows x 64 halves per parity (float4 copies) ----
        #pragma unroll
        for (int t = 0; t < 2; t++) {
            int idx = tid + t * 512;     // 0..1023
            int row = idx >> 3, cq = idx & 7;
            int sidx = row * 96 + c * 8 + cq;           // float4 index in g_A*
            ((float4*)sAe)[row * 9 + cq] = ((const float4*)g_Ae)[sidx];
            ((float4*)sAo)[row * 9 + cq] = ((const float4*)g_Ao)[sidx];
        }

        // ---- build B_e / B_o rows for 32 j's of this chunk ----
        for (int idx = tid; idx < 32 * 130; idx += 512) {
            int jl = idx / 130, i = idx - jl * 130;
            int j = c * 32 + jl;
            int q = j >> 7, ci = j & 127;
            int pos = m0 - 1 + i;
            float v = (pos >= 0 && pos < LIN) ? xb[(size_t)ci * LIN + pos] : 0.f;
            float p = (q == 0) ? v : (q == 1) ? v * v : v * v * v;
            __half h = __float2half_rn(p);
            int r0 = 2 * jl * PB, r1 = r0 + PB;
            if (i < 128) sBe[r0 + i] = h;                       // tap0, shift -1
            if (i >= 1 && i < 129) {
                sBe[r1 + (i - 1)] = h;                          // tap1, shift 0
                sBo[r0 + (i - 1)] = h;                          // tap0, shift 0
            }
            if (i >= 2) sBo[r1 + (i - 2)] = h;                  // tap1, shift +1
        }
        __syncthreads();

        // ---- 4 k-steps of 16 ----
        #pragma unroll
        for (int ks = 0; ks < 4; ks++) {
            uint32_t aE[2][4], aO[2][4], bE[2][4], bO[2][4];
            uint32_t ko = ks * 32;                              // 16 halves
            ldsm_x4(aE[0], aE0 + ko);
            ldsm_x4(aE[1], aE0 + ko + 16 * PA * 2);
            ldsm_x4(aO[0], aO0 + ko);
            ldsm_x4(aO[1], aO0 + ko + 16 * PA * 2);
            uint32_t kb = ks * 16 * PB * 2;
            ldsm_x4t(bE[0], bE0 + kb);
            ldsm_x4t(bE[1], bE0 + kb + 32);                     // +16 cols
            ldsm_x4t(bO[0], bO0 + kb);
            ldsm_x4t(bO[1], bO0 + kb + 32);
            #pragma unroll
            for (int mt = 0; mt < 2; mt++)
                #pragma unroll
                for (int nt = 0; nt < 4; nt++) {
                    int nb = nt >> 1, pr = (nt & 1) * 2;
                    mma16816(acc[0][mt][nt], aE[mt], bE[nb][pr], bE[nb][pr + 1]);
                    mma16816(acc[1][mt][nt], aO[mt], bO[nb][pr], bO[nb][pr + 1]);
                }
        }
    }

    // ---- epilogue: bias, interleaved float4 stores, stats ----
    #pragma unroll
    for (int mt = 0; mt < 2; mt++) {
        #pragma unroll
        for (int half = 0; half < 2; half++) {
            int co = co0 + mt * 16 + (lane >> 2) + half * 8;
            float bv = __ldg(&bias[co]);
            float* orow = out + (size_t)(b * COUT + co) * LOUT + 2 * m0;
            float s = 0.f, ss = 0.f;
            #pragma unroll
            for (int nt = 0; nt < 4; nt++) {
                float e0 = acc[0][mt][nt][half * 2 + 0] + bv;
                float e1 = acc[0][mt][nt][half * 2 + 1] + bv;
                float o0 = acc[1][mt][nt][half * 2 + 0] + bv;
                float o1 = acc[1][mt][nt][half * 2 + 1] + bv;
                int m = mbase + nt * 8 + (lane & 3) * 2;
                *(float4*)(orow + 2 * m) = make_float4(e0, o0, e1, o1);
                s  += e0 + o0 + e1 + o1;
                ss += e0 * e0 + o0 * o0 + e1 * e1 + o1 * o1;
            }
            s  += __shfl_xor_sync(0xffffffffu, s, 1);
            s  += __shfl_xor_sync(0xffffffffu, s, 2);
            ss += __shfl_xor_sync(0xffffffffu, ss, 1);
            ss += __shfl_xor_sync(0xffffffffu, ss, 2);
            if ((lane & 3) == 0) {
                int cl = mt * 16 + (lane >> 2) + half * 8;
                sWS [w * 32 + cl] = s;
                sWSq[w * 32 + cl] = ss;
            }
        }
    }
    __syncthreads();
    if (tid < 128) {
        int co = tid, cs = co >> 5, cl = co & 31;
        float s = 0.f, ss = 0.f;
        #pragma unroll
        for (int i = 0; i < 4; i++) {
            s  += sWS [(cs * 4 + i) * 32 + cl];
            ss += sWSq[(cs * 4 + i) * 32 + cl];
        }
        int pidx = (b * NT + tile) * COUT + co;
        g_psum[pidx]   = s;
        g_psumsq[pidx] = ss;
    }
}

// ---------------------------------------------------------------------------
// Kernel 3: reduce per-tile partials -> mean, rstd (fp64 accumulation)
// ---------------------------------------------------------------------------
__global__ void reduce_stats() {
    int idx = blockIdx.x * blockDim.x + threadIdx.x;
    if (idx >= BATCH * COUT) return;
    int b = idx / COUT, co = idx % COUT;
    double s = 0.0, ss = 0.0;
    for (int t = 0; t < NT; t++) {
        int p = (b * NT + t) * COUT + co;
        s  += (double)g_psum[p];
        ss += (double)g_psumsq[p];
    }
    double mean = s / (double)LOUT;
    double var  = ss / (double)LOUT - mean * mean;
    g_stats[idx * 2 + 0] = (float)mean;
    g_stats[idx * 2 + 1] = (float)(1.0 / sqrt(var + 1e-5));
}

// ---------------------------------------------------------------------------
// Kernel 4: normalize + tanh
// ---------------------------------------------------------------------------
__global__ void norm_tanh(float* __restrict__ out) {
    const int total4 = BATCH * COUT * LOUT / 4;
    float4* o4 = (float4*)out;
    for (int idx4 = blockIdx.x * blockDim.x + threadIdx.x; idx4 < total4;
         idx4 += gridDim.x * blockDim.x) {
        int row = idx4 >> 12;
        float mean = g_stats[row * 2 + 0];
        float rstd = g_stats[row * 2 + 1];
        float4 v = o4[idx4];
        v.x = tanhf((v.x - mean) * rstd);
        v.y = tanhf((v.y - mean) * rstd);
        v.z = tanhf((v.z - mean) * rstd);
        v.w = tanhf((v.w - mean) * rstd);
        o4[idx4] = v;
    }
}

// ---------------------------------------------------------------------------
extern "C" void kernel_launch(void* const* d_in, const int* in_sizes, int n_in,
                              void* d_out, int out_size) {
    const float* x    = (const float*)d_in[0];
    const float* W    = (const float*)d_in[1];
    const float* bias = (const float*)d_in[2];
    float* out = (float*)d_out;

    cudaFuncSetAttribute(conv_kernel,
                         cudaFuncAttributeMaxDynamicSharedMemorySize, SM_TOTAL);

    prep_weights<<<(COUT * 384 + 255) / 256, 256>>>(W);
    conv_kernel<<<dim3(NT, BATCH), 512, SM_TOTAL>>>(x, bias, out);
    reduce_stats<<<(BATCH * COUT + 255) / 256, 256>>>();
    norm_tanh<<<8192, 256>>>(out);
}

// round 4
// speedup vs baseline: 4.9135x; 1.5530x over previous
#include <cuda_runtime.h>
#include <cuda_fp16.h>
#include <math.h>
#include <stdint.h>

#define BATCH 16
#define CIN   128
#define LIN   8192
#define LOUT  16384
#define COUT  128
#define NMT   128                // original-m per CTA tile (-> 256 outputs)
#define NT    (LIN / NMT)        // 64
#define KTOT  768                // 2 taps * 384 power-channels
#define NCHUNK 12                // 12 chunks of K=64
#define PA    72                 // A smem pitch (halves)
#define PB    136                // B smem pitch (halves)
#define PX    136                // x tile pitch (floats)

// ---------------- scratch ----------------
__device__ __half g_Ae[COUT * KTOT];
__device__ __half g_Ao[COUT * KTOT];
__device__ float  g_psum  [BATCH * NT * COUT];
__device__ float  g_psumsq[BATCH * NT * COUT];
__device__ float  g_stats [BATCH * COUT * 2];

// ---------------- smem byte offsets ----------------
#define OFF_X   0                        // 128*136*4 = 69632
#define OFF_A   69632                    // 2 buf * 36864 = 73728
#define A_BUF_STRIDE 36864
#define A_PAR_STRIDE 18432
#define OFF_B   143360                   // 2 buf * 34816 = 69632
#define B_BUF_STRIDE 34816
#define B_PAR_STRIDE 17408
#define OFF_WS  212992
#define OFF_WSQ 215040
#define SM_TOTAL 217088

// ---------------- PTX helpers (family-portable) ----------------
__device__ __forceinline__ uint32_t smem_u32(const void* p) {
    uint32_t a;
    asm("{ .reg .u64 t; cvta.to.shared.u64 t, %1; cvt.u32.u64 %0, t; }" : "=r"(a) : "l"(p));
    return a;
}
#define CP_ASYNC16(dst, src) \
    asm volatile("cp.async.cg.shared.global [%0], [%1], 16;" :: "r"(dst), "l"(src) : "memory")
#define CP_COMMIT() asm volatile("cp.async.commit_group;" ::: "memory")
#define CP_WAIT(n)  asm volatile("cp.async.wait_group %0;" :: "n"(n) : "memory")

__device__ __forceinline__ void ldsm_x4(uint32_t* r, uint32_t addr) {
    asm volatile("ldmatrix.sync.aligned.m8n8.x4.shared.b16 {%0,%1,%2,%3}, [%4];"
        : "=r"(r[0]), "=r"(r[1]), "=r"(r[2]), "=r"(r[3]) : "r"(addr));
}
__device__ __forceinline__ void ldsm_x4t(uint32_t* r, uint32_t addr) {
    asm volatile("ldmatrix.sync.aligned.m8n8.x4.trans.shared.b16 {%0,%1,%2,%3}, [%4];"
        : "=r"(r[0]), "=r"(r[1]), "=r"(r[2]), "=r"(r[3]) : "r"(addr));
}
__device__ __forceinline__ void mma16816(float* d, const uint32_t* a, uint32_t b0, uint32_t b1) {
    asm volatile("mma.sync.aligned.m16n8k16.row.col.f32.f16.f16.f32 "
        "{%0,%1,%2,%3}, {%4,%5,%6,%7}, {%8,%9}, {%0,%1,%2,%3};"
        : "+f"(d[0]), "+f"(d[1]), "+f"(d[2]), "+f"(d[3])
        : "r"(a[0]), "r"(a[1]), "r"(a[2]), "r"(a[3]), "r"(b0), "r"(b1));
}
__device__ __forceinline__ uint32_t pk(float a, float b) {
    __half2 h = __floats2half2_rn(a, b);
    return *(uint32_t*)&h;
}

// ---------------------------------------------------------------------------
// Kernel 1: fold W into fp16 even/odd weight images, K interleaved as 2j+tap.
//   even: out[2m]   = W0*p[m-1] + (W1+W2)*p[m]
//   odd:  out[2m+1] = (W0+W1)*p[m] + W2*p[m+1]
// ---------------------------------------------------------------------------
__global__ void prep_weights(const float* __restrict__ W) {
    int idx = blockIdx.x * blockDim.x + threadIdx.x;
    if (idx >= COUT * 384) return;
    int co = idx / 384, j = idx % 384;
    const float* wp = W + (size_t)idx * 3;
    float w0 = wp[0], w1 = wp[1], w2 = wp[2];
    g_Ae[co * KTOT + 2 * j + 0] = __float2half_rn(w0);
    g_Ae[co * KTOT + 2 * j + 1] = __float2half_rn(w1 + w2);
    g_Ao[co * KTOT + 2 * j + 0] = __float2half_rn(w0 + w1);
    g_Ao[co * KTOT + 2 * j + 1] = __float2half_rn(w2);
}

// ---------------------------------------------------------------------------
// B-build for chunk c1: powers from fp32 x tile in SMEM, shifted taps via
// shared uint4s. One task per thread.
// ---------------------------------------------------------------------------
__device__ __forceinline__ void buildB(char* smem, int c1, int tid) {
    const int buf = c1 & 1;
    const int q   = c1 >> 2;
    const int jl  = tid >> 4, oct = tid & 15;
    const int ci  = ((c1 & 3) << 5) + jl;
    const int i0  = oct << 3;
    const float4* xr = (const float4*)(smem + OFF_X + (size_t)ci * PX * 4) + (i0 >> 2);
    float4 F0 = xr[0], F1 = xr[1], F2 = xr[2], F3 = xr[3];
    float v0 = F0.w, v1 = F1.x, v2 = F1.y, v3 = F1.z, v4 = F1.w,
          v5 = F2.x, v6 = F2.y, v7 = F2.z, v8 = F2.w, v9 = F3.x;
    if (q == 1) {
        v0 *= v0; v1 *= v1; v2 *= v2; v3 *= v3; v4 *= v4;
        v5 *= v5; v6 *= v6; v7 *= v7; v8 *= v8; v9 *= v9;
    } else if (q == 2) {
        v0 = v0*v0*v0; v1 = v1*v1*v1; v2 = v2*v2*v2; v3 = v3*v3*v3; v4 = v4*v4*v4;
        v5 = v5*v5*v5; v6 = v6*v6*v6; v7 = v7*v7*v7; v8 = v8*v8*v8; v9 = v9*v9*v9;
    }
    uint32_t P0 = pk(v0, v1), P1 = pk(v2, v3), P2 = pk(v4, v5), P3 = pk(v6, v7), P4 = pk(v8, v9);
    uint32_t Q0 = pk(v1, v2), Q1 = pk(v3, v4), Q2 = pk(v5, v6), Q3 = pk(v7, v8);
    char* be = smem + OFF_B + buf * B_BUF_STRIDE + (size_t)(2 * jl) * (PB * 2) + i0 * 2;
    char* bo = be + B_PAR_STRIDE;
    *(uint4*)be            = make_uint4(P0, P1, P2, P3);   // B_e tap0: p[m-1]
    *(uint4*)(be + PB * 2) = make_uint4(Q0, Q1, Q2, Q3);   // B_e tap1: p[m]
    *(uint4*)bo            = make_uint4(Q0, Q1, Q2, Q3);   // B_o tap0: p[m]
    *(uint4*)(bo + PB * 2) = make_uint4(P1, P2, P3, P4);   // B_o tap1: p[m+1]
}

// ---------------------------------------------------------------------------
__device__ __forceinline__ void mma_step(float (&acc)[2][2][4][4],
        uint32_t aE0, uint32_t aO0, uint32_t bE0, uint32_t bO0, int ks) {
    uint32_t aE[2][4], aO[2][4], bE[2][4], bO[2][4];
    uint32_t ko = ks * 32;
    ldsm_x4(aE[0], aE0 + ko);
    ldsm_x4(aE[1], aE0 + ko + 16 * PA * 2);
    ldsm_x4(aO[0], aO0 + ko);
    ldsm_x4(aO[1], aO0 + ko + 16 * PA * 2);
    uint32_t kb = ks * 16 * PB * 2;
    ldsm_x4t(bE[0], bE0 + kb);
    ldsm_x4t(bE[1], bE0 + kb + 32);
    ldsm_x4t(bO[0], bO0 + kb);
    ldsm_x4t(bO[1], bO0 + kb + 32);
    #pragma unroll
    for (int mt = 0; mt < 2; mt++)
        #pragma unroll
        for (int nt = 0; nt < 4; nt++) {
            int nb = nt >> 1, pr = (nt & 1) * 2;
            mma16816(acc[0][mt][nt], aE[mt], bE[nb][pr], bE[nb][pr + 1]);
            mma16816(acc[1][mt][nt], aO[mt], bO[nb][pr], bO[nb][pr + 1]);
        }
}

// ---------------------------------------------------------------------------
// Kernel 2: pipelined HMMA conv. Grid (NT, BATCH), 512 threads = 16 warps.
// ---------------------------------------------------------------------------
__global__ __launch_bounds__(512, 1)
void conv_kernel(const float* __restrict__ x,
                 const float* __restrict__ bias,
                 float* __restrict__ out) {
    extern __shared__ char smem[];
    const uint32_t sb = smem_u32(smem);
    const int b    = blockIdx.y;
    const int tile = blockIdx.x;
    const int m0   = tile * NMT;
    const int tid  = threadIdx.x;
    const int lane = tid & 31;
    const int w    = tid >> 5;
    const int co0   = (w >> 2) * 32;
    const int mbase = (w & 3) * 32;

    const float* xb = x + (size_t)b * CIN * LIN;

    // ---- prologue: cp.async x-tile interior + A[0] ----
    #pragma unroll
    for (int t = 0; t < 8; t++) {
        int idx = tid + t * 512;
        int r = idx >> 5, tq = idx & 31;
        uint32_t dst = sb + OFF_X + (uint32_t)((r * PX + 4 + tq * 4) * 4);
        const float* src = xb + (size_t)r * LIN + m0 + tq * 4;
        CP_ASYNC16(dst, src);
    }
    #pragma unroll
    for (int t = 0; t < 4; t++) {
        int idx = tid + t * 512;
        int par = idx >> 10, r = (idx >> 3) & 127, cq = idx & 7;
        uint32_t dst = sb + OFF_A + par * A_PAR_STRIDE + (uint32_t)(r * PA * 2 + cq * 16);
        const __half* src = (par ? g_Ao : g_Ae) + (size_t)r * KTOT + cq * 8;
        CP_ASYNC16(dst, src);
    }
    CP_COMMIT();
    // halo edges (scalar, zero-filled out of range)
    if (tid < 256) {
        int ci = tid >> 1, side = tid & 1;
        int pos = side ? (m0 + NMT) : (m0 - 1);
        int col = side ? 132 : 3;
        float v = (pos >= 0 && pos < LIN) ? xb[(size_t)ci * LIN + pos] : 0.f;
        *(float*)(smem + OFF_X + (size_t)(ci * PX + col) * 4) = v;
    }
    CP_WAIT(0);
    __syncthreads();
    buildB(smem, 0, tid);

    float acc[2][2][4][4];
    #pragma unroll
    for (int p = 0; p < 2; p++)
        #pragma unroll
        for (int mt = 0; mt < 2; mt++)
            #pragma unroll
            for (int nt = 0; nt < 4; nt++)
                #pragma unroll
                for (int r = 0; r < 4; r++) acc[p][mt][nt][r] = 0.f;

    const uint32_t aRow = lane & 15, aColq = lane >> 4;
    const uint32_t a_off = (uint32_t)(((co0 + aRow) * PA + aColq * 8) * 2);
    const uint32_t b_off = (uint32_t)((aRow * PB + mbase + aColq * 8) * 2);

    for (int c = 0; c < NCHUNK; c++) {
        CP_WAIT(0);          // own A[c] copies complete
        __syncthreads();     // everyone's A[c]/B[c] visible; prev MMA done
        if (c + 1 < NCHUNK) {
            #pragma unroll
            for (int t = 0; t < 4; t++) {
                int idx = tid + t * 512;
                int par = idx >> 10, r = (idx >> 3) & 127, cq = idx & 7;
                uint32_t dst = sb + OFF_A + ((c + 1) & 1) * A_BUF_STRIDE
                             + par * A_PAR_STRIDE + (uint32_t)(r * PA * 2 + cq * 16);
                const __half* src = (par ? g_Ao : g_Ae) + (size_t)r * KTOT + (c + 1) * 64 + cq * 8;
                CP_ASYNC16(dst, src);
            }
            CP_COMMIT();
        }
        uint32_t aE0 = sb + OFF_A + (c & 1) * A_BUF_STRIDE + a_off;
        uint32_t aO0 = aE0 + A_PAR_STRIDE;
        uint32_t bE0 = sb + OFF_B + (c & 1) * B_BUF_STRIDE + b_off;
        uint32_t bO0 = bE0 + B_PAR_STRIDE;

        mma_step(acc, aE0, aO0, bE0, bO0, 0);
        mma_step(acc, aE0, aO0, bE0, bO0, 1);
        if (c + 1 < NCHUNK) buildB(smem, c + 1, tid);   // hidden under MMA
        mma_step(acc, aE0, aO0, bE0, bO0, 2);
        mma_step(acc, aE0, aO0, bE0, bO0, 3);
    }

    // ---- epilogue: bias, interleaved float4 stores, stats ----
    float* sWS  = (float*)(smem + OFF_WS);
    float* sWSq = (float*)(smem + OFF_WSQ);
    #pragma unroll
    for (int mt = 0; mt < 2; mt++) {
        #pragma unroll
        for (int half = 0; half < 2; half++) {
            int co = co0 + mt * 16 + (lane >> 2) + half * 8;
            float bv = __ldg(&bias[co]);
            float* orow = out + (size_t)(b * COUT + co) * LOUT + 2 * m0;
            float s = 0.f, ss = 0.f;
            #pragma unroll
            for (int nt = 0; nt < 4; nt++) {
                float e0 = acc[0][mt][nt][half * 2 + 0] + bv;
                float e1 = acc[0][mt][nt][half * 2 + 1] + bv;
                float o0 = acc[1][mt][nt][half * 2 + 0] + bv;
                float o1 = acc[1][mt][nt][half * 2 + 1] + bv;
                int m = mbase + nt * 8 + (lane & 3) * 2;
                *(float4*)(orow + 2 * m) = make_float4(e0, o0, e1, o1);
                s  += e0 + o0 + e1 + o1;
                ss += e0 * e0 + o0 * o0 + e1 * e1 + o1 * o1;
            }
            s  += __shfl_xor_sync(0xffffffffu, s, 1);
            s  += __shfl_xor_sync(0xffffffffu, s, 2);
            ss += __shfl_xor_sync(0xffffffffu, ss, 1);
            ss += __shfl_xor_sync(0xffffffffu, ss, 2);
            if ((lane & 3) == 0) {
                int cl = mt * 16 + (lane >> 2) + half * 8;
                sWS [w * 32 + cl] = s;
                sWSq[w * 32 + cl] = ss;
            }
        }
    }
    __syncthreads();
    if (tid < 128) {
        int co = tid, cs = co >> 5, cl = co & 31;
        float s = 0.f, ss = 0.f;
        #pragma unroll
        for (int i = 0; i < 4; i++) {
            s  += sWS [(cs * 4 + i) * 32 + cl];
            ss += sWSq[(cs * 4 + i) * 32 + cl];
        }
        int pidx = (b * NT + tile) * COUT + co;
        g_psum[pidx]   = s;
        g_psumsq[pidx] = ss;
    }
}

// ---------------------------------------------------------------------------
// Kernel 3: reduce per-tile partials -> mean, rstd (fp64 accumulation)
// ---------------------------------------------------------------------------
__global__ void reduce_stats() {
    int idx = blockIdx.x * blockDim.x + threadIdx.x;
    if (idx >= BATCH * COUT) return;
    int b = idx / COUT, co = idx % COUT;
    double s = 0.0, ss = 0.0;
    for (int t = 0; t < NT; t++) {
        int p = (b * NT + t) * COUT + co;
        s  += (double)g_psum[p];
        ss += (double)g_psumsq[p];
    }
    double mean = s / (double)LOUT;
    double var  = ss / (double)LOUT - mean * mean;
    g_stats[idx * 2 + 0] = (float)mean;
    g_stats[idx * 2 + 1] = (float)(1.0 / sqrt(var + 1e-5));
}

// ---------------------------------------------------------------------------
// Kernel 4: normalize + tanh
// ---------------------------------------------------------------------------
__global__ void norm_tanh(float* __restrict__ out) {
    const int total4 = BATCH * COUT * LOUT / 4;
    float4* o4 = (float4*)out;
    for (int idx4 = blockIdx.x * blockDim.x + threadIdx.x; idx4 < total4;
         idx4 += gridDim.x * blockDim.x) {
        int row = idx4 >> 12;
        float mean = g_stats[row * 2 + 0];
        float rstd = g_stats[row * 2 + 1];
        float4 v = o4[idx4];
        v.x = tanhf((v.x - mean) * rstd);
        v.y = tanhf((v.y - mean) * rstd);
        v.z = tanhf((v.z - mean) * rstd);
        v.w = tanhf((v.w - mean) * rstd);
        o4[idx4] = v;
    }
}

// ---------------------------------------------------------------------------
extern "C" void kernel_launch(void* const* d_in, const int* in_sizes, int n_in,
                              void* d_out, int out_size) {
    const float* x    = (const float*)d_in[0];
    const float* W    = (const float*)d_in[1];
    const float* bias = (const float*)d_in[2];
    float* out = (float*)d_out;

    cudaFuncSetAttribute(conv_kernel,
                         cudaFuncAttributeMaxDynamicSharedMemorySize, SM_TOTAL);

    prep_weights<<<(COUT * 384 + 255) / 256, 256>>>(W);
    conv_kernel<<<dim3(NT, BATCH), 512, SM_TOTAL>>>(x, bias, out);
    reduce_stats<<<(BATCH * COUT + 255) / 256, 256>>>();
    norm_tanh<<<8192, 256>>>(out);
}

// round 5
// speedup vs baseline: 5.4612x; 1.1115x over previous
#include <cuda_runtime.h>
#include <cuda_fp16.h>
#include <math.h>
#include <stdint.h>

#define BATCH 16
#define CIN   128
#define LIN   8192
#define LOUT  16384
#define COUT  128
#define NMT   128                // original-m per CTA tile (-> 256 outputs)
#define NT    (LIN / NMT)        // 64
#define KTOT  768                // 2 taps * 384 power-channels
#define NCHUNK 12                // chunks of K=64
#define PA    72                 // A smem pitch (halves)
#define PB    136                // B smem pitch (halves)
#define PX    136                // x tile pitch (floats)

// ---------------- scratch ----------------
__device__ __half g_Ae[COUT * KTOT];
__device__ __half g_Ao[COUT * KTOT];
__device__ __half g_mid[(size_t)BATCH * COUT * LOUT];   // fp16 conv output (64 MB)
__device__ float  g_psum  [BATCH * NT * COUT];
__device__ float  g_psumsq[BATCH * NT * COUT];
__device__ float  g_stats [BATCH * COUT * 2];

// ---------------- smem byte offsets ----------------
#define OFF_X   0                        // 128*136*4 = 69632
#define OFF_A   69632
#define A_BUF_STRIDE 36864
#define A_PAR_STRIDE 18432
#define OFF_B   143360
#define B_BUF_STRIDE 34816
#define B_PAR_STRIDE 17408
#define OFF_WS  212992
#define OFF_WSQ 215040
#define SM_TOTAL 217088

// ---------------- PTX helpers (family-portable) ----------------
__device__ __forceinline__ uint32_t smem_u32(const void* p) {
    uint32_t a;
    asm("{ .reg .u64 t; cvta.to.shared.u64 t, %1; cvt.u32.u64 %0, t; }" : "=r"(a) : "l"(p));
    return a;
}
#define CP_ASYNC16(dst, src) \
    asm volatile("cp.async.cg.shared.global [%0], [%1], 16;" :: "r"(dst), "l"(src) : "memory")
#define CP_COMMIT() asm volatile("cp.async.commit_group;" ::: "memory")
#define CP_WAIT(n)  asm volatile("cp.async.wait_group %0;" :: "n"(n) : "memory")

__device__ __forceinline__ void ldsm_x4(uint32_t* r, uint32_t addr) {
    asm volatile("ldmatrix.sync.aligned.m8n8.x4.shared.b16 {%0,%1,%2,%3}, [%4];"
        : "=r"(r[0]), "=r"(r[1]), "=r"(r[2]), "=r"(r[3]) : "r"(addr));
}
__device__ __forceinline__ void ldsm_x4t(uint32_t* r, uint32_t addr) {
    asm volatile("ldmatrix.sync.aligned.m8n8.x4.trans.shared.b16 {%0,%1,%2,%3}, [%4];"
        : "=r"(r[0]), "=r"(r[1]), "=r"(r[2]), "=r"(r[3]) : "r"(addr));
}
__device__ __forceinline__ void mma16816(float* d, const uint32_t* a, uint32_t b0, uint32_t b1) {
    asm volatile("mma.sync.aligned.m16n8k16.row.col.f32.f16.f16.f32 "
        "{%0,%1,%2,%3}, {%4,%5,%6,%7}, {%8,%9}, {%0,%1,%2,%3};"
        : "+f"(d[0]), "+f"(d[1]), "+f"(d[2]), "+f"(d[3])
        : "r"(a[0]), "r"(a[1]), "r"(a[2]), "r"(a[3]), "r"(b0), "r"(b1));
}
__device__ __forceinline__ uint32_t pk(float a, float b) {
    __half2 h = __floats2half2_rn(a, b);
    return *(uint32_t*)&h;
}

// ---------------------------------------------------------------------------
// Kernel 1: fold W into fp16 even/odd weight images, K interleaved as 2j+tap.
// ---------------------------------------------------------------------------
__global__ void prep_weights(const float* __restrict__ W) {
    int idx = blockIdx.x * blockDim.x + threadIdx.x;
    if (idx >= COUT * 384) return;
    int co = idx / 384, j = idx % 384;
    const float* wp = W + (size_t)idx * 3;
    float w0 = wp[0], w1 = wp[1], w2 = wp[2];
    g_Ae[co * KTOT + 2 * j + 0] = __float2half_rn(w0);
    g_Ae[co * KTOT + 2 * j + 1] = __float2half_rn(w1 + w2);
    g_Ao[co * KTOT + 2 * j + 0] = __float2half_rn(w0 + w1);
    g_Ao[co * KTOT + 2 * j + 1] = __float2half_rn(w2);
}

// ---------------------------------------------------------------------------
// B-build for chunk c1 from fp32 x tile in SMEM. One task per thread.
// ---------------------------------------------------------------------------
__device__ __forceinline__ void buildB(char* smem, int c1, int tid) {
    const int buf = c1 & 1;
    const int q   = c1 >> 2;
    const int jl  = tid >> 4, oct = tid & 15;
    const int ci  = ((c1 & 3) << 5) + jl;
    const int i0  = oct << 3;
    const float4* xr = (const float4*)(smem + OFF_X + (size_t)ci * PX * 4) + (i0 >> 2);
    float4 F0 = xr[0], F1 = xr[1], F2 = xr[2], F3 = xr[3];
    float v0 = F0.w, v1 = F1.x, v2 = F1.y, v3 = F1.z, v4 = F1.w,
          v5 = F2.x, v6 = F2.y, v7 = F2.z, v8 = F2.w, v9 = F3.x;
    if (q == 1) {
        v0 *= v0; v1 *= v1; v2 *= v2; v3 *= v3; v4 *= v4;
        v5 *= v5; v6 *= v6; v7 *= v7; v8 *= v8; v9 *= v9;
    } else if (q == 2) {
        v0 = v0*v0*v0; v1 = v1*v1*v1; v2 = v2*v2*v2; v3 = v3*v3*v3; v4 = v4*v4*v4;
        v5 = v5*v5*v5; v6 = v6*v6*v6; v7 = v7*v7*v7; v8 = v8*v8*v8; v9 = v9*v9*v9;
    }
    uint32_t P0 = pk(v0, v1), P1 = pk(v2, v3), P2 = pk(v4, v5), P3 = pk(v6, v7), P4 = pk(v8, v9);
    uint32_t Q0 = pk(v1, v2), Q1 = pk(v3, v4), Q2 = pk(v5, v6), Q3 = pk(v7, v8);
    char* be = smem + OFF_B + buf * B_BUF_STRIDE + (size_t)(2 * jl) * (PB * 2) + i0 * 2;
    char* bo = be + B_PAR_STRIDE;
    *(uint4*)be            = make_uint4(P0, P1, P2, P3);   // B_e tap0: p[m-1]
    *(uint4*)(be + PB * 2) = make_uint4(Q0, Q1, Q2, Q3);   // B_e tap1: p[m]
    *(uint4*)bo            = make_uint4(Q0, Q1, Q2, Q3);   // B_o tap0: p[m]
    *(uint4*)(bo + PB * 2) = make_uint4(P1, P2, P3, P4);   // B_o tap1: p[m+1]
}

// ---------------------------------------------------------------------------
__device__ __forceinline__ void ldA(uint32_t (&aE)[2][4], uint32_t (&aO)[2][4],
                                    uint32_t aE0, uint32_t aO0, int ks) {
    uint32_t ko = ks * 32;
    ldsm_x4(aE[0], aE0 + ko);
    ldsm_x4(aE[1], aE0 + ko + 16 * PA * 2);
    ldsm_x4(aO[0], aO0 + ko);
    ldsm_x4(aO[1], aO0 + ko + 16 * PA * 2);
}
__device__ __forceinline__ void ldB(uint32_t (&bE)[2][4], uint32_t (&bO)[2][4],
                                    uint32_t bE0, uint32_t bO0, int ks) {
    uint32_t kb = ks * 16 * PB * 2;
    ldsm_x4t(bE[0], bE0 + kb);
    ldsm_x4t(bE[1], bE0 + kb + 32);
    ldsm_x4t(bO[0], bO0 + kb);
    ldsm_x4t(bO[1], bO0 + kb + 32);
}
__device__ __forceinline__ void mmas(float (&acc)[2][2][4][4],
        uint32_t (&aE)[2][4], uint32_t (&aO)[2][4],
        uint32_t (&bE)[2][4], uint32_t (&bO)[2][4]) {
    #pragma unroll
    for (int mt = 0; mt < 2; mt++)
        #pragma unroll
        for (int nt = 0; nt < 4; nt++) {
            int nb = nt >> 1, pr = (nt & 1) * 2;
            mma16816(acc[0][mt][nt], aE[mt], bE[nb][pr], bE[nb][pr + 1]);
            mma16816(acc[1][mt][nt], aO[mt], bO[nb][pr], bO[nb][pr + 1]);
        }
}

// ---------------------------------------------------------------------------
// Kernel 2: pipelined HMMA conv. Grid (NT, BATCH), 512 threads = 16 warps.
// ---------------------------------------------------------------------------
__global__ __launch_bounds__(512, 1)
void conv_kernel(const float* __restrict__ x,
                 const float* __restrict__ bias) {
    extern __shared__ char smem[];
    const uint32_t sb = smem_u32(smem);
    const int b    = blockIdx.y;
    const int tile = blockIdx.x;
    const int m0   = tile * NMT;
    const int tid  = threadIdx.x;
    const int lane = tid & 31;
    const int w    = tid >> 5;
    const int co0   = (w >> 2) * 32;
    const int mbase = (w & 3) * 32;

    const float* xb = x + (size_t)b * CIN * LIN;

    // ---- prologue: cp.async x-tile interior + A[0] ----
    #pragma unroll
    for (int t = 0; t < 8; t++) {
        int idx = tid + t * 512;
        int r = idx >> 5, tq = idx & 31;
        uint32_t dst = sb + OFF_X + (uint32_t)((r * PX + 4 + tq * 4) * 4);
        const float* src = xb + (size_t)r * LIN + m0 + tq * 4;
        CP_ASYNC16(dst, src);
    }
    #pragma unroll
    for (int t = 0; t < 4; t++) {
        int idx = tid + t * 512;
        int par = idx >> 10, r = (idx >> 3) & 127, cq = idx & 7;
        uint32_t dst = sb + OFF_A + par * A_PAR_STRIDE + (uint32_t)(r * PA * 2 + cq * 16);
        const __half* src = (par ? g_Ao : g_Ae) + (size_t)r * KTOT + cq * 8;
        CP_ASYNC16(dst, src);
    }
    CP_COMMIT();
    if (tid < 256) {
        int ci = tid >> 1, side = tid & 1;
        int pos = side ? (m0 + NMT) : (m0 - 1);
        int col = side ? 132 : 3;
        float v = (pos >= 0 && pos < LIN) ? xb[(size_t)ci * LIN + pos] : 0.f;
        *(float*)(smem + OFF_X + (size_t)(ci * PX + col) * 4) = v;
    }
    CP_WAIT(0);
    __syncthreads();
    buildB(smem, 0, tid);

    float acc[2][2][4][4];
    #pragma unroll
    for (int p = 0; p < 2; p++)
        #pragma unroll
        for (int mt = 0; mt < 2; mt++)
            #pragma unroll
            for (int nt = 0; nt < 4; nt++)
                #pragma unroll
                for (int r = 0; r < 4; r++) acc[p][mt][nt][r] = 0.f;

    const uint32_t aRow = lane & 15, aColq = lane >> 4;
    const uint32_t a_off = (uint32_t)(((co0 + aRow) * PA + aColq * 8) * 2);
    const uint32_t b_off = (uint32_t)((aRow * PB + mbase + aColq * 8) * 2);

    for (int c = 0; c < NCHUNK; c++) {
        CP_WAIT(0);
        __syncthreads();
        if (c + 1 < NCHUNK) {
            #pragma unroll
            for (int t = 0; t < 4; t++) {
                int idx = tid + t * 512;
                int par = idx >> 10, r = (idx >> 3) & 127, cq = idx & 7;
                uint32_t dst = sb + OFF_A + ((c + 1) & 1) * A_BUF_STRIDE
                             + par * A_PAR_STRIDE + (uint32_t)(r * PA * 2 + cq * 16);
                const __half* src = (par ? g_Ao : g_Ae) + (size_t)r * KTOT + (c + 1) * 64 + cq * 8;
                CP_ASYNC16(dst, src);
            }
            CP_COMMIT();
        }
        uint32_t aE0 = sb + OFF_A + (c & 1) * A_BUF_STRIDE + a_off;
        uint32_t aO0 = aE0 + A_PAR_STRIDE;
        uint32_t bE0 = sb + OFF_B + (c & 1) * B_BUF_STRIDE + b_off;
        uint32_t bO0 = bE0 + B_PAR_STRIDE;

        // software-pipelined k-steps: B frags double-buffered
        uint32_t aE[2][4], aO[2][4];
        uint32_t bE[2][2][4], bO[2][2][4];
        ldB(bE[0], bO[0], bE0, bO0, 0);
        #pragma unroll
        for (int ks = 0; ks < 4; ks++) {
            const int cur = ks & 1;
            ldA(aE, aO, aE0, aO0, ks);
            if (ks < 3) ldB(bE[cur ^ 1], bO[cur ^ 1], bE0, bO0, ks + 1);
            mmas(acc, aE, aO, bE[cur], bO[cur]);
            if (ks == 1 && c + 1 < NCHUNK) buildB(smem, c + 1, tid);
        }
    }

    // ---- epilogue: bias, fp16 interleaved stores to g_mid, stats ----
    float* sWS  = (float*)(smem + OFF_WS);
    float* sWSq = (float*)(smem + OFF_WSQ);
    #pragma unroll
    for (int mt = 0; mt < 2; mt++) {
        #pragma unroll
        for (int half = 0; half < 2; half++) {
            int co = co0 + mt * 16 + (lane >> 2) + half * 8;
            float bv = __ldg(&bias[co]);
            __half* mrow = g_mid + (size_t)(b * COUT + co) * LOUT + 2 * m0;
            float s = 0.f, ss = 0.f;
            #pragma unroll
            for (int nt = 0; nt < 4; nt++) {
                float e0 = acc[0][mt][nt][half * 2 + 0] + bv;
                float e1 = acc[0][mt][nt][half * 2 + 1] + bv;
                float o0 = acc[1][mt][nt][half * 2 + 0] + bv;
                float o1 = acc[1][mt][nt][half * 2 + 1] + bv;
                int m = mbase + nt * 8 + (lane & 3) * 2;
                *(uint2*)(mrow + 2 * m) = make_uint2(pk(e0, o0), pk(e1, o1));
                s  += e0 + o0 + e1 + o1;
                ss += e0 * e0 + o0 * o0 + e1 * e1 + o1 * o1;
            }
            s  += __shfl_xor_sync(0xffffffffu, s, 1);
            s  += __shfl_xor_sync(0xffffffffu, s, 2);
            ss += __shfl_xor_sync(0xffffffffu, ss, 1);
            ss += __shfl_xor_sync(0xffffffffu, ss, 2);
            if ((lane & 3) == 0) {
                int cl = mt * 16 + (lane >> 2) + half * 8;
                sWS [w * 32 + cl] = s;
                sWSq[w * 32 + cl] = ss;
            }
        }
    }
    __syncthreads();
    if (tid < 128) {
        int co = tid, cs = co >> 5, cl = co & 31;
        float s = 0.f, ss = 0.f;
        #pragma unroll
        for (int i = 0; i < 4; i++) {
            s  += sWS [(cs * 4 + i) * 32 + cl];
            ss += sWSq[(cs * 4 + i) * 32 + cl];
        }
        int pidx = (b * NT + tile) * COUT + co;
        g_psum[pidx]   = s;
        g_psumsq[pidx] = ss;
    }
}

// ---------------------------------------------------------------------------
// Kernel 3: one warp per (b,co) row; fp32 shuffle-tree over 64 partials.
// ---------------------------------------------------------------------------
__global__ void reduce_stats() {
    int row = blockIdx.x;                 // b*COUT + co
    int b = row >> 7, co = row & 127;
    int lane = threadIdx.x;
    float s = 0.f, ss = 0.f;
    #pragma unroll
    for (int h = 0; h < 2; h++) {
        int t = lane + h * 32;
        int p = (b * NT + t) * COUT + co;
        s  += g_psum[p];
        ss += g_psumsq[p];
    }
    #pragma unroll
    for (int off = 16; off > 0; off >>= 1) {
        s  += __shfl_xor_sync(0xffffffffu, s, off);
        ss += __shfl_xor_sync(0xffffffffu, ss, off);
    }
    if (lane == 0) {
        double mean = (double)s / (double)LOUT;
        double var  = (double)ss / (double)LOUT - mean * mean;
        g_stats[row * 2 + 0] = (float)mean;
        g_stats[row * 2 + 1] = (float)(1.0 / sqrt(var + 1e-5));
    }
}

// ---------------------------------------------------------------------------
// Kernel 4: normalize + tanh: read fp16 mid, write fp32 out.
// ---------------------------------------------------------------------------
__global__ void norm_tanh(float* __restrict__ out) {
    const int total8 = BATCH * COUT * LOUT / 8;
    const uint4* m8 = (const uint4*)g_mid;
    float4* o4 = (float4*)out;
    for (int idx = blockIdx.x * blockDim.x + threadIdx.x; idx < total8;
         idx += gridDim.x * blockDim.x) {
        int row = idx >> 11;                  // 16384/8 = 2048 uint4 per row
        float mean = g_stats[row * 2 + 0];
        float rstd = g_stats[row * 2 + 1];
        uint4 v = m8[idx];
        float2 a0 = __half22float2(*(__half2*)&v.x);
        float2 a1 = __half22float2(*(__half2*)&v.y);
        float2 a2 = __half22float2(*(__half2*)&v.z);
        float2 a3 = __half22float2(*(__half2*)&v.w);
        float4 r0, r1;
        r0.x = tanhf((a0.x - mean) * rstd);
        r0.y = tanhf((a0.y - mean) * rstd);
        r0.z = tanhf((a1.x - mean) * rstd);
        r0.w = tanhf((a1.y - mean) * rstd);
        r1.x = tanhf((a2.x - mean) * rstd);
        r1.y = tanhf((a2.y - mean) * rstd);
        r1.z = tanhf((a3.x - mean) * rstd);
        r1.w = tanhf((a3.y - mean) * rstd);
        o4[idx * 2 + 0] = r0;
        o4[idx * 2 + 1] = r1;
    }
}

// ---------------------------------------------------------------------------
extern "C" void kernel_launch(void* const* d_in, const int* in_sizes, int n_in,
                              void* d_out, int out_size) {
    const float* x    = (const float*)d_in[0];
    const float* W    = (const float*)d_in[1];
    const float* bias = (const float*)d_in[2];
    float* out = (float*)d_out;

    cudaFuncSetAttribute(conv_kernel,
                         cudaFuncAttributeMaxDynamicSharedMemorySize, SM_TOTAL);

    prep_weights<<<(COUT * 384 + 255) / 256, 256>>>(W);
    conv_kernel<<<dim3(NT, BATCH), 512, SM_TOTAL>>>(x, bias);
    reduce_stats<<<BATCH * COUT, 32>>>();
    norm_tanh<<<4096, 256>>>(out);
}

// round 6
// speedup vs baseline: 5.6080x; 1.0269x over previous
#include <cuda_runtime.h>
#include <cuda_fp16.h>
#include <math.h>
#include <stdint.h>

#define BATCH 16
#define CIN   128
#define LIN   8192
#define LOUT  16384
#define COUT  128
#define NMT   128                // original-m per CTA tile (-> 256 outputs)
#define NT    (LIN / NMT)        // 64
#define KTOT  768
#define NCHUNK 12                // chunks of K=64
#define PA    72                 // A smem pitch (halves)
#define PB    136                // B smem pitch (halves)
#define PX    136                // x tile pitch (floats)
#define PM    264                // epilogue staging pitch (halves), conflict-free

// ---------------- scratch ----------------
__device__ __half g_Ae[COUT * KTOT];
__device__ __half g_Ao[COUT * KTOT];
__device__ __half g_mid[(size_t)BATCH * COUT * LOUT];   // fp16 conv output
__device__ float  g_psum  [BATCH * NT * COUT];
__device__ float  g_psumsq[BATCH * NT * COUT];
__device__ float  g_stats [BATCH * COUT * 2];

// ---------------- smem byte offsets ----------------
#define OFF_X   0                        // 128*136*4 = 69632
#define OFF_A   69632
#define A_BUF_STRIDE 36864
#define A_PAR_STRIDE 18432
#define OFF_B   143360                   // also reused as epilogue staging (67584 B)
#define B_BUF_STRIDE 34816
#define B_PAR_STRIDE 17408
#define OFF_WS  212992
#define OFF_WSQ 215040
#define SM_TOTAL 217088

// ---------------- PTX helpers (family-portable) ----------------
__device__ __forceinline__ uint32_t smem_u32(const void* p) {
    uint32_t a;
    asm("{ .reg .u64 t; cvta.to.shared.u64 t, %1; cvt.u32.u64 %0, t; }" : "=r"(a) : "l"(p));
    return a;
}
#define CP_ASYNC16(dst, src) \
    asm volatile("cp.async.cg.shared.global [%0], [%1], 16;" :: "r"(dst), "l"(src) : "memory")
#define CP_COMMIT() asm volatile("cp.async.commit_group;" ::: "memory")
#define CP_WAIT(n)  asm volatile("cp.async.wait_group %0;" :: "n"(n) : "memory")

__device__ __forceinline__ void ldsm_x4(uint32_t* r, uint32_t addr) {
    asm volatile("ldmatrix.sync.aligned.m8n8.x4.shared.b16 {%0,%1,%2,%3}, [%4];"
        : "=r"(r[0]), "=r"(r[1]), "=r"(r[2]), "=r"(r[3]) : "r"(addr));
}
__device__ __forceinline__ void ldsm_x4t(uint32_t* r, uint32_t addr) {
    asm volatile("ldmatrix.sync.aligned.m8n8.x4.trans.shared.b16 {%0,%1,%2,%3}, [%4];"
        : "=r"(r[0]), "=r"(r[1]), "=r"(r[2]), "=r"(r[3]) : "r"(addr));
}
__device__ __forceinline__ void mma16816(float* d, const uint32_t* a, uint32_t b0, uint32_t b1) {
    asm volatile("mma.sync.aligned.m16n8k16.row.col.f32.f16.f16.f32 "
        "{%0,%1,%2,%3}, {%4,%5,%6,%7}, {%8,%9}, {%0,%1,%2,%3};"
        : "+f"(d[0]), "+f"(d[1]), "+f"(d[2]), "+f"(d[3])
        : "r"(a[0]), "r"(a[1]), "r"(a[2]), "r"(a[3]), "r"(b0), "r"(b1));
}
__device__ __forceinline__ uint32_t pk(float a, float b) {
    __half2 h = __floats2half2_rn(a, b);
    return *(uint32_t*)&h;
}

// ---------------------------------------------------------------------------
// Kernel 1: fold W into fp16 even/odd weight images, K interleaved as 2j+tap.
// ---------------------------------------------------------------------------
__global__ void prep_weights(const float* __restrict__ W) {
    int idx = blockIdx.x * blockDim.x + threadIdx.x;
    if (idx >= COUT * 384) return;
    int co = idx / 384, j = idx % 384;
    const float* wp = W + (size_t)idx * 3;
    float w0 = wp[0], w1 = wp[1], w2 = wp[2];
    g_Ae[co * KTOT + 2 * j + 0] = __float2half_rn(w0);
    g_Ae[co * KTOT + 2 * j + 1] = __float2half_rn(w1 + w2);
    g_Ao[co * KTOT + 2 * j + 0] = __float2half_rn(w0 + w1);
    g_Ao[co * KTOT + 2 * j + 1] = __float2half_rn(w2);
}

// ---------------------------------------------------------------------------
// B-build for chunk c1 from fp32 x tile in SMEM. One task per thread.
// ---------------------------------------------------------------------------
__device__ __forceinline__ void buildB(char* smem, int c1, int tid) {
    const int buf = c1 & 1;
    const int q   = c1 >> 2;
    const int jl  = tid >> 4, oct = tid & 15;
    const int ci  = ((c1 & 3) << 5) + jl;
    const int i0  = oct << 3;
    const float4* xr = (const float4*)(smem + OFF_X + (size_t)ci * PX * 4) + (i0 >> 2);
    float4 F0 = xr[0], F1 = xr[1], F2 = xr[2], F3 = xr[3];
    float v0 = F0.w, v1 = F1.x, v2 = F1.y, v3 = F1.z, v4 = F1.w,
          v5 = F2.x, v6 = F2.y, v7 = F2.z, v8 = F2.w, v9 = F3.x;
    if (q == 1) {
        v0 *= v0; v1 *= v1; v2 *= v2; v3 *= v3; v4 *= v4;
        v5 *= v5; v6 *= v6; v7 *= v7; v8 *= v8; v9 *= v9;
    } else if (q == 2) {
        v0 = v0*v0*v0; v1 = v1*v1*v1; v2 = v2*v2*v2; v3 = v3*v3*v3; v4 = v4*v4*v4;
        v5 = v5*v5*v5; v6 = v6*v6*v6; v7 = v7*v7*v7; v8 = v8*v8*v8; v9 = v9*v9*v9;
    }
    uint32_t P0 = pk(v0, v1), P1 = pk(v2, v3), P2 = pk(v4, v5), P3 = pk(v6, v7), P4 = pk(v8, v9);
    uint32_t Q0 = pk(v1, v2), Q1 = pk(v3, v4), Q2 = pk(v5, v6), Q3 = pk(v7, v8);
    char* be = smem + OFF_B + buf * B_BUF_STRIDE + (size_t)(2 * jl) * (PB * 2) + i0 * 2;
    char* bo = be + B_PAR_STRIDE;
    *(uint4*)be            = make_uint4(P0, P1, P2, P3);   // B_e tap0: p[m-1]
    *(uint4*)(be + PB * 2) = make_uint4(Q0, Q1, Q2, Q3);   // B_e tap1: p[m]
    *(uint4*)bo            = make_uint4(Q0, Q1, Q2, Q3);   // B_o tap0: p[m]
    *(uint4*)(bo + PB * 2) = make_uint4(P1, P2, P3, P4);   // B_o tap1: p[m+1]
}

// ---------------------------------------------------------------------------
// Kernel 2: parity-split HMMA conv. Grid (NT, BATCH), 512 threads = 16 warps.
// Warp = one parity, 32co x 64m.
// ---------------------------------------------------------------------------
__global__ __launch_bounds__(512, 1)
void conv_kernel(const float* __restrict__ x,
                 const float* __restrict__ bias) {
    extern __shared__ char smem[];
    const uint32_t sb = smem_u32(smem);
    const int b    = blockIdx.y;
    const int tile = blockIdx.x;
    const int m0   = tile * NMT;
    const int tid  = threadIdx.x;
    const int lane = tid & 31;
    const int w    = tid >> 5;
    const int par   = w >> 3;            // 0 = even, 1 = odd
    const int cs    = (w >> 1) & 3;      // co strip
    const int mb    = w & 1;             // m block
    const int co0   = cs * 32;
    const int mbase = mb * 64;

    const float* xb = x + (size_t)b * CIN * LIN;

    // ---- prologue: cp.async x-tile interior + A[0] ----
    #pragma unroll
    for (int t = 0; t < 8; t++) {
        int idx = tid + t * 512;
        int r = idx >> 5, tq = idx & 31;
        uint32_t dst = sb + OFF_X + (uint32_t)((r * PX + 4 + tq * 4) * 4);
        const float* src = xb + (size_t)r * LIN + m0 + tq * 4;
        CP_ASYNC16(dst, src);
    }
    #pragma unroll
    for (int t = 0; t < 4; t++) {
        int idx = tid + t * 512;
        int p2 = idx >> 10, r = (idx >> 3) & 127, cq = idx & 7;
        uint32_t dst = sb + OFF_A + p2 * A_PAR_STRIDE + (uint32_t)(r * PA * 2 + cq * 16);
        const __half* src = (p2 ? g_Ao : g_Ae) + (size_t)r * KTOT + cq * 8;
        CP_ASYNC16(dst, src);
    }
    CP_COMMIT();
    if (tid < 256) {
        int ci = tid >> 1, side = tid & 1;
        int pos = side ? (m0 + NMT) : (m0 - 1);
        int col = side ? 132 : 3;
        float v = (pos >= 0 && pos < LIN) ? xb[(size_t)ci * LIN + pos] : 0.f;
        *(float*)(smem + OFF_X + (size_t)(ci * PX + col) * 4) = v;
    }
    CP_WAIT(0);
    __syncthreads();
    buildB(smem, 0, tid);

    float acc[2][8][4];                  // [mt][nt][reg]
    #pragma unroll
    for (int mt = 0; mt < 2; mt++)
        #pragma unroll
        for (int nt = 0; nt < 8; nt++)
            #pragma unroll
            for (int r = 0; r < 4; r++) acc[mt][nt][r] = 0.f;

    const uint32_t aRow = lane & 15, aColq = lane >> 4;
    const uint32_t a_off = (uint32_t)(par * A_PAR_STRIDE + ((co0 + aRow) * PA + aColq * 8) * 2);
    const uint32_t b_off = (uint32_t)(par * B_PAR_STRIDE + (aRow * PB + mbase + aColq * 8) * 2);

    for (int c = 0; c < NCHUNK; c++) {
        CP_WAIT(0);
        __syncthreads();
        if (c + 1 < NCHUNK) {
            #pragma unroll
            for (int t = 0; t < 4; t++) {
                int idx = tid + t * 512;
                int p2 = idx >> 10, r = (idx >> 3) & 127, cq = idx & 7;
                uint32_t dst = sb + OFF_A + ((c + 1) & 1) * A_BUF_STRIDE
                             + p2 * A_PAR_STRIDE + (uint32_t)(r * PA * 2 + cq * 16);
                const __half* src = (p2 ? g_Ao : g_Ae) + (size_t)r * KTOT + (c + 1) * 64 + cq * 8;
                CP_ASYNC16(dst, src);
            }
            CP_COMMIT();
        }
        const uint32_t aB = sb + OFF_A + (c & 1) * A_BUF_STRIDE + a_off;
        const uint32_t bB = sb + OFF_B + (c & 1) * B_BUF_STRIDE + b_off;

        uint32_t af[2][4];
        uint32_t bf[2][4][4];            // [buf][nb][reg]
        #pragma unroll
        for (int nb = 0; nb < 4; nb++) ldsm_x4t(bf[0][nb], bB + nb * 32);

        #pragma unroll
        for (int ks = 0; ks < 4; ks++) {
            const int cur = ks & 1;
            ldsm_x4(af[0], aB + ks * 32);
            ldsm_x4(af[1], aB + ks * 32 + 16 * PA * 2);
            if (ks < 3) {
                uint32_t bk = bB + (ks + 1) * 16 * PB * 2;
                #pragma unroll
                for (int nb = 0; nb < 4; nb++) ldsm_x4t(bf[cur ^ 1][nb], bk + nb * 32);
            }
            #pragma unroll
            for (int mt = 0; mt < 2; mt++)
                #pragma unroll
                for (int nt = 0; nt < 8; nt++) {
                    int nb = nt >> 1, pr = (nt & 1) * 2;
                    mma16816(acc[mt][nt], af[mt], bf[cur][nb][pr], bf[cur][nb][pr + 1]);
                }
            if (ks == 1 && c + 1 < NCHUNK) buildB(smem, c + 1, tid);
        }
    }

    // ---- epilogue: stage fp16 tile in SMEM (reuse B area), stats ----
    __syncthreads();                     // all mma done before overwriting B area
    __half* sMid = (__half*)(smem + OFF_B);
    float* sWS  = (float*)(smem + OFF_WS);
    float* sWSq = (float*)(smem + OFF_WSQ);
    #pragma unroll
    for (int mt = 0; mt < 2; mt++) {
        #pragma unroll
        for (int half = 0; half < 2; half++) {
            int co = co0 + mt * 16 + (lane >> 2) + half * 8;
            float bv = __ldg(&bias[co]);
            float s = 0.f, ss = 0.f;
            #pragma unroll
            for (int nt = 0; nt < 8; nt++) {
                float v0 = acc[mt][nt][half * 2 + 0] + bv;
                float v1 = acc[mt][nt][half * 2 + 1] + bv;
                int m = mbase + nt * 8 + (lane & 3) * 2;
                sMid[co * PM + 2 * m + par]       = __float2half_rn(v0);
                sMid[co * PM + 2 * (m + 1) + par] = __float2half_rn(v1);
                s  += v0 + v1;
                ss += v0 * v0 + v1 * v1;
            }
            s  += __shfl_xor_sync(0xffffffffu, s, 1);
            s  += __shfl_xor_sync(0xffffffffu, s, 2);
            ss += __shfl_xor_sync(0xffffffffu, ss, 1);
            ss += __shfl_xor_sync(0xffffffffu, ss, 2);
            if ((lane & 3) == 0) {
                int cl = mt * 16 + (lane >> 2) + half * 8;
                sWS [w * 32 + cl] = s;
                sWSq[w * 32 + cl] = ss;
            }
        }
    }
    __syncthreads();
    // final stats reduce: 4 warps (2 par x 2 mb) contribute to each co
    if (tid < 128) {
        int co = tid, cs2 = co >> 5, cl = co & 31;
        float s = 0.f, ss = 0.f;
        #pragma unroll
        for (int p2 = 0; p2 < 2; p2++)
            #pragma unroll
            for (int mb2 = 0; mb2 < 2; mb2++) {
                int w2 = p2 * 8 + cs2 * 2 + mb2;
                s  += sWS [w2 * 32 + cl];
                ss += sWSq[w2 * 32 + cl];
            }
        int pidx = (b * NT + tile) * COUT + co;
        g_psum[pidx]   = s;
        g_psumsq[pidx] = ss;
    }
    // coalesced copy sMid -> g_mid
    #pragma unroll
    for (int t = 0; t < 8; t++) {
        int i = tid + t * 512;
        int row = i >> 5, cq = i & 31;
        uint4 v = *(uint4*)(sMid + row * PM + cq * 8);
        *(uint4*)(g_mid + (size_t)(b * COUT + row) * LOUT + 2 * m0 + cq * 8) = v;
    }
}

// ---------------------------------------------------------------------------
// Kernel 3: one warp per (b,co) row; fp32 shuffle-tree over 64 partials.
// ---------------------------------------------------------------------------
__global__ void reduce_stats() {
    int row = blockIdx.x;
    int b = row >> 7, co = row & 127;
    int lane = threadIdx.x;
    float s = 0.f, ss = 0.f;
    #pragma unroll
    for (int h = 0; h < 2; h++) {
        int t = lane + h * 32;
        int p = (b * NT + t) * COUT + co;
        s  += g_psum[p];
        ss += g_psumsq[p];
    }
    #pragma unroll
    for (int off = 16; off > 0; off >>= 1) {
        s  += __shfl_xor_sync(0xffffffffu, s, off);
        ss += __shfl_xor_sync(0xffffffffu, ss, off);
    }
    if (lane == 0) {
        double mean = (double)s / (double)LOUT;
        double var  = (double)ss / (double)LOUT - mean * mean;
        g_stats[row * 2 + 0] = (float)mean;
        g_stats[row * 2 + 1] = (float)(1.0 / sqrt(var + 1e-5));
    }
}

// ---------------------------------------------------------------------------
// Kernel 4: normalize + tanh: read fp16 mid, write fp32 out.
// ---------------------------------------------------------------------------
__global__ void norm_tanh(float* __restrict__ out) {
    const int total8 = BATCH * COUT * LOUT / 8;
    const uint4* m8 = (const uint4*)g_mid;
    float4* o4 = (float4*)out;
    for (int idx = blockIdx.x * blockDim.x + threadIdx.x; idx < total8;
         idx += gridDim.x * blockDim.x) {
        int row = idx >> 11;
        float mean = g_stats[row * 2 + 0];
        float rstd = g_stats[row * 2 + 1];
        uint4 v = m8[idx];
        float2 a0 = __half22float2(*(__half2*)&v.x);
        float2 a1 = __half22float2(*(__half2*)&v.y);
        float2 a2 = __half22float2(*(__half2*)&v.z);
        float2 a3 = __half22float2(*(__half2*)&v.w);
        float4 r0, r1;
        r0.x = tanhf((a0.x - mean) * rstd);
        r0.y = tanhf((a0.y - mean) * rstd);
        r0.z = tanhf((a1.x - mean) * rstd);
        r0.w = tanhf((a1.y - mean) * rstd);
        r1.x = tanhf((a2.x - mean) * rstd);
        r1.y = tanhf((a2.y - mean) * rstd);
        r1.z = tanhf((a3.x - mean) * rstd);
        r1.w = tanhf((a3.y - mean) * rstd);
        o4[idx * 2 + 0] = r0;
        o4[idx * 2 + 1] = r1;
    }
}

// ---------------------------------------------------------------------------
extern "C" void kernel_launch(void* const* d_in, const int* in_sizes, int n_in,
                              void* d_out, int out_size) {
    const float* x    = (const float*)d_in[0];
    const float* W    = (const float*)d_in[1];
    const float* bias = (const float*)d_in[2];
    float* out = (float*)d_out;

    cudaFuncSetAttribute(conv_kernel,
                         cudaFuncAttributeMaxDynamicSharedMemorySize, SM_TOTAL);

    prep_weights<<<(COUT * 384 + 255) / 256, 256>>>(W);
    conv_kernel<<<dim3(NT, BATCH), 512, SM_TOTAL>>>(x, bias);
    reduce_stats<<<BATCH * COUT, 32>>>();
    norm_tanh<<<4096, 256>>>(out);
}